// round 1
// baseline (speedup 1.0000x reference)
#include <cuda_runtime.h>
#include <cstdint>

#define B_  2
#define N_  2048
#define D_  1024
#define H_  8
#define DK_ 128
#define DV_ 1024

// Static scratch (allocation guards forbid cudaMalloc).
// Q, K stored d-major: [B*H][DK][N].  V stored row-major: [B*H][N][DV].
__device__ float g_Q[(size_t)B_ * H_ * DK_ * N_];   // 16 MB
__device__ float g_K[(size_t)B_ * H_ * DK_ * N_];   // 16 MB
__device__ float g_V[(size_t)B_ * H_ * N_ * DV_];   // 128 MB

// ---------------------------------------------------------------------------
// Projection GEMM: out[bh, n, e] (TR=false) or out[bh, e, n] (TR=true)
//   = sum_d X[b, n, d] * W[h, e, d]
// 128x128 block tile, BK=16, 256 threads, 8x8 microtile, float4 everywhere.
// ---------------------------------------------------------------------------
template <bool TR>
__global__ __launch_bounds__(256) void proj_kernel(
    const float* __restrict__ X, const float* __restrict__ W,
    float* __restrict__ out, int E) {
  __shared__ float As[16][128];  // [k][m]
  __shared__ float Bs[16][128];  // [k][e]

  const int bh = blockIdx.z;
  const int b  = bh >> 3;
  const int h  = bh & 7;
  const int n0 = blockIdx.y * 128;
  const int e0 = blockIdx.x * 128;

  const float* A  = X + ((size_t)b * N_ + n0) * D_;
  const float* Bw = W + ((size_t)h * E + e0) * D_;

  const int tid = threadIdx.x;
  const int tx = tid & 15;
  const int ty = tid >> 4;

  float acc[8][8] = {};

  for (int k0 = 0; k0 < D_; k0 += 16) {
#pragma unroll
    for (int r = 0; r < 2; ++r) {
      int f   = tid + 256 * r;     // 0..511 float4 slots
      int row = f >> 2;            // 0..127
      int k4  = (f & 3) * 4;       // 0,4,8,12
      float4 va = *(const float4*)(A + (size_t)row * D_ + k0 + k4);
      As[k4 + 0][row] = va.x; As[k4 + 1][row] = va.y;
      As[k4 + 2][row] = va.z; As[k4 + 3][row] = va.w;
      float4 vb = *(const float4*)(Bw + (size_t)row * D_ + k0 + k4);
      Bs[k4 + 0][row] = vb.x; Bs[k4 + 1][row] = vb.y;
      Bs[k4 + 2][row] = vb.z; Bs[k4 + 3][row] = vb.w;
    }
    __syncthreads();

#pragma unroll
    for (int k = 0; k < 16; ++k) {
      float a[8], bb[8];
      *(float4*)&a[0]  = *(const float4*)&As[k][ty * 8];
      *(float4*)&a[4]  = *(const float4*)&As[k][ty * 8 + 4];
      *(float4*)&bb[0] = *(const float4*)&Bs[k][tx * 8];
      *(float4*)&bb[4] = *(const float4*)&Bs[k][tx * 8 + 4];
#pragma unroll
      for (int i = 0; i < 8; ++i)
#pragma unroll
        for (int j = 0; j < 8; ++j) acc[i][j] += a[i] * bb[j];
    }
    __syncthreads();
  }

  if (TR) {
    // out[bh][e][n]
#pragma unroll
    for (int j = 0; j < 8; ++j) {
      int e = e0 + tx * 8 + j;
      float* op = out + ((size_t)bh * E + e) * N_ + n0 + ty * 8;
      *(float4*)op       = make_float4(acc[0][j], acc[1][j], acc[2][j], acc[3][j]);
      *(float4*)(op + 4) = make_float4(acc[4][j], acc[5][j], acc[6][j], acc[7][j]);
    }
  } else {
    // out[bh][n][e]
#pragma unroll
    for (int i = 0; i < 8; ++i) {
      int n = n0 + ty * 8 + i;
      float* op = out + ((size_t)bh * N_ + n) * E + e0 + tx * 8;
      *(float4*)op       = make_float4(acc[i][0], acc[i][1], acc[i][2], acc[i][3]);
      *(float4*)(op + 4) = make_float4(acc[i][4], acc[i][5], acc[i][6], acc[i][7]);
    }
  }
}

// ---------------------------------------------------------------------------
// Fused causal relu-attention + residual.
// Block: (v-chunk x, q-tile y, batch z). 256 threads.
//   Loops heads and causal key tiles; accumulates O[64][128] in registers.
//   sim = relu(Q K^T) masked(m<=n) / N ;  out = x + sum_h sim @ V
// ---------------------------------------------------------------------------
__global__ __launch_bounds__(256) void attn_kernel(
    const float* __restrict__ X, float* __restrict__ out) {
  extern __shared__ float sm[];
  float* Qt = sm;               // [128][64]  d-major
  float* Kt = Qt + 128 * 64;    // [128][64]  d-major
  float* Vs = Kt + 128 * 64;    // [64][128]  key-major
  float* Ss = Vs + 64 * 128;    // [64][65]   padded

  const int b  = blockIdx.z;
  const int q0 = blockIdx.y * 64;
  const int v0 = blockIdx.x * 128;
  const int tid = threadIdx.x;
  const int tx = tid & 15;
  const int ty = tid >> 4;
  const float invN = 1.0f / (float)N_;

  float O[4][8] = {};

  for (int h = 0; h < H_; ++h) {
    const size_t bh = (size_t)(b * H_ + h);
    const float* Qg = g_Q + bh * DK_ * N_ + q0;   // [DK][N] slice, col offset q0
    __syncthreads();  // previous iteration fully done before overwriting Qt
#pragma unroll
    for (int r = 0; r < 8; ++r) {
      int f  = tid + 256 * r;    // 0..2047 float4 slots (128 d x 16)
      int d  = f >> 4;
      int i4 = (f & 15) * 4;
      *(float4*)&Qt[d * 64 + i4] = *(const float4*)(Qg + (size_t)d * N_ + i4);
    }
    __syncthreads();

    for (int k0 = 0; k0 <= q0; k0 += 64) {
      const float* Kg = g_K + bh * DK_ * N_ + k0;
      const float* Vg = g_V + (bh * N_ + k0) * DV_ + v0;
#pragma unroll
      for (int r = 0; r < 8; ++r) {
        int f  = tid + 256 * r;
        int d  = f >> 4;
        int i4 = (f & 15) * 4;
        *(float4*)&Kt[d * 64 + i4] = *(const float4*)(Kg + (size_t)d * N_ + i4);
        int row = f >> 5;          // 0..63
        int c4  = (f & 31) * 4;    // 0..124
        *(float4*)&Vs[row * 128 + c4] = *(const float4*)(Vg + (size_t)row * DV_ + c4);
      }
      __syncthreads();

      // S[64x64] = Q K^T  (outer product over d, k-major smem: conflict-free)
      float s[4][4] = {};
#pragma unroll 4
      for (int d = 0; d < DK_; ++d) {
        float4 qa = *(const float4*)&Qt[d * 64 + ty * 4];
        float4 ka = *(const float4*)&Kt[d * 64 + tx * 4];
        float qv[4] = {qa.x, qa.y, qa.z, qa.w};
        float kv[4] = {ka.x, ka.y, ka.z, ka.w};
#pragma unroll
        for (int i = 0; i < 4; ++i)
#pragma unroll
          for (int j = 0; j < 4; ++j) s[i][j] += qv[i] * kv[j];
      }

      // mask + relu + 1/N, stash in padded smem
#pragma unroll
      for (int i = 0; i < 4; ++i) {
        int n = q0 + ty * 4 + i;
#pragma unroll
        for (int j = 0; j < 4; ++j) {
          int m = k0 + tx * 4 + j;
          float val = (m <= n) ? fmaxf(s[i][j], 0.0f) * invN : 0.0f;
          Ss[(ty * 4 + i) * 65 + tx * 4 + j] = val;
        }
      }
      __syncthreads();

      // O += S @ V
#pragma unroll 4
      for (int j = 0; j < 64; ++j) {
        float4 va = *(const float4*)&Vs[j * 128 + tx * 8];
        float4 vb = *(const float4*)&Vs[j * 128 + tx * 8 + 4];
        float vv[8] = {va.x, va.y, va.z, va.w, vb.x, vb.y, vb.z, vb.w};
#pragma unroll
        for (int i = 0; i < 4; ++i) {
          float sv = Ss[(ty * 4 + i) * 65 + j];
#pragma unroll
          for (int c = 0; c < 8; ++c) O[i][c] += sv * vv[c];
        }
      }
      __syncthreads();
    }
  }

  // epilogue: out = x + O
#pragma unroll
  for (int i = 0; i < 4; ++i) {
    size_t base = ((size_t)b * N_ + q0 + ty * 4 + i) * DV_ + v0 + tx * 8;
    float4 x0 = *(const float4*)(X + base);
    float4 x1 = *(const float4*)(X + base + 4);
    *(float4*)(out + base) =
        make_float4(x0.x + O[i][0], x0.y + O[i][1], x0.z + O[i][2], x0.w + O[i][3]);
    *(float4*)(out + base + 4) =
        make_float4(x1.x + O[i][4], x1.y + O[i][5], x1.z + O[i][6], x1.w + O[i][7]);
  }
}

// ---------------------------------------------------------------------------
extern "C" void kernel_launch(void* const* d_in, const int* in_sizes, int n_in,
                              void* d_out, int out_size) {
  const float* x  = (const float*)d_in[0];
  const float* Wq = (const float*)d_in[1];
  const float* Wk = (const float*)d_in[2];
  const float* Wv = (const float*)d_in[3];
  float* out = (float*)d_out;

  float *Qp, *Kp, *Vp;
  cudaGetSymbolAddress((void**)&Qp, g_Q);
  cudaGetSymbolAddress((void**)&Kp, g_K);
  cudaGetSymbolAddress((void**)&Vp, g_V);

  dim3 blk(256);
  // Q, K transposed to d-major; V row-major.
  proj_kernel<true><<<dim3(1, 16, 16), blk>>>(x, Wq, Qp, DK_);
  proj_kernel<true><<<dim3(1, 16, 16), blk>>>(x, Wk, Kp, DK_);
  proj_kernel<false><<<dim3(8, 16, 16), blk>>>(x, Wv, Vp, DV_);

  size_t smem = (size_t)(128 * 64 * 2 + 64 * 128 + 64 * 65) * sizeof(float);
  cudaFuncSetAttribute(attn_kernel, cudaFuncAttributeMaxDynamicSharedMemorySize,
                       (int)smem);
  attn_kernel<<<dim3(8, 32, 2), blk, smem>>>(x, out);
}

// round 2
// speedup vs baseline: 8.2115x; 8.2115x over previous
#include <cuda_runtime.h>
#include <cuda_bf16.h>
#include <cstdint>

#define B_  2
#define N_  2048
#define D_  1024
#define H_  8
#define DK_ 128
#define DV_ 1024

using bf16 = __nv_bfloat16;

// Static scratch (no cudaMalloc allowed).
__device__ bf16 g_Xb [(size_t)B_ * N_ * D_];        //  8.4 MB
__device__ bf16 g_Wqb[(size_t)H_ * DK_ * D_];       //  2.1 MB
__device__ bf16 g_Wkb[(size_t)H_ * DK_ * D_];       //  2.1 MB
__device__ bf16 g_Wvb[(size_t)H_ * DV_ * D_];       // 16.8 MB
__device__ bf16 g_Q  [(size_t)B_ * H_ * N_ * DK_];  //  8.4 MB
__device__ bf16 g_K  [(size_t)B_ * H_ * N_ * DK_];  //  8.4 MB
__device__ bf16 g_V  [(size_t)B_ * H_ * N_ * DV_];  //   64 MB

// ---------------------------------------------------------------------------
// helpers
// ---------------------------------------------------------------------------
__device__ __forceinline__ uint32_t smem_u32(const void* p) {
  return (uint32_t)__cvta_generic_to_shared(p);
}
__device__ __forceinline__ void ldmx4(uint32_t& r0, uint32_t& r1, uint32_t& r2,
                                      uint32_t& r3, uint32_t addr) {
  asm volatile("ldmatrix.sync.aligned.m8n8.x4.shared.b16 {%0,%1,%2,%3},[%4];"
               : "=r"(r0), "=r"(r1), "=r"(r2), "=r"(r3) : "r"(addr));
}
__device__ __forceinline__ void ldmx4t(uint32_t& r0, uint32_t& r1, uint32_t& r2,
                                       uint32_t& r3, uint32_t addr) {
  asm volatile("ldmatrix.sync.aligned.m8n8.x4.trans.shared.b16 {%0,%1,%2,%3},[%4];"
               : "=r"(r0), "=r"(r1), "=r"(r2), "=r"(r3) : "r"(addr));
}
__device__ __forceinline__ void mma16816(float* c, uint32_t a0, uint32_t a1,
                                         uint32_t a2, uint32_t a3, uint32_t b0,
                                         uint32_t b1) {
  asm volatile(
      "mma.sync.aligned.m16n8k16.row.col.f32.bf16.bf16.f32 "
      "{%0,%1,%2,%3},{%4,%5,%6,%7},{%8,%9},{%0,%1,%2,%3};"
      : "+f"(c[0]), "+f"(c[1]), "+f"(c[2]), "+f"(c[3])
      : "r"(a0), "r"(a1), "r"(a2), "r"(a3), "r"(b0), "r"(b1));
}
// pack two f32 -> bf16x2 (lo = first arg)
__device__ __forceinline__ uint32_t packbf(float lo, float hi) {
  uint32_t r;
  asm("cvt.rn.bf16x2.f32 %0, %1, %2;" : "=r"(r) : "f"(hi), "f"(lo));
  return r;
}

// ---------------------------------------------------------------------------
// fp32 -> bf16 cast (vectorized)
// ---------------------------------------------------------------------------
__global__ void cast_kernel(const float* __restrict__ src, bf16* __restrict__ dst,
                            int n4) {
  int i = blockIdx.x * blockDim.x + threadIdx.x;
  if (i < n4) {
    float4 v = ((const float4*)src)[i];
    __nv_bfloat162 lo = __floats2bfloat162_rn(v.x, v.y);
    __nv_bfloat162 hi = __floats2bfloat162_rn(v.z, v.w);
    ((__nv_bfloat162*)dst)[2 * i]     = lo;
    ((__nv_bfloat162*)dst)[2 * i + 1] = hi;
  }
}

// ---------------------------------------------------------------------------
// Projection GEMM (bf16 HMMA): out[bh][n][e] = sum_d X[b,n,d] * W[h,e,d]
// 128x128 tile, 8 warps, k-step 64. smem stride 72 elems (144B) ->
// ldmatrix conflict-free.
// ---------------------------------------------------------------------------
template <int E>
__global__ __launch_bounds__(256) void proj_mma(const bf16* __restrict__ Xb,
                                                const bf16* __restrict__ Wb,
                                                bf16* __restrict__ out) {
  __shared__ bf16 Xs[128 * 72];
  __shared__ bf16 Ws[128 * 72];

  const int bh = blockIdx.z, b = bh >> 3, h = bh & 7;
  const int n0 = blockIdx.y * 128, e0 = blockIdx.x * 128;
  const bf16* Xg = Xb + ((size_t)(b * N_ + n0)) * D_;
  const bf16* Wg = Wb + ((size_t)h * E + e0) * (size_t)D_;

  const int tid = threadIdx.x, warp = tid >> 5, lane = tid & 31;
  const int gid = lane >> 2, tig = lane & 3;
  const int m0 = warp * 16;
  const uint32_t xs = smem_u32(Xs), ws = smem_u32(Ws);

  float acc[16][4] = {};

  for (int k0 = 0; k0 < D_; k0 += 64) {
#pragma unroll
    for (int r = 0; r < 4; ++r) {
      int f = tid + 256 * r;
      int row = f >> 3, c8 = (f & 7) * 8;
      *(uint4*)&Xs[row * 72 + c8] = *(const uint4*)(Xg + (size_t)row * D_ + k0 + c8);
      *(uint4*)&Ws[row * 72 + c8] = *(const uint4*)(Wg + (size_t)row * D_ + k0 + c8);
    }
    __syncthreads();

#pragma unroll
    for (int kk = 0; kk < 64; kk += 16) {
      uint32_t a0, a1, a2, a3;
      {
        int m = lane >> 3;
        int row = m0 + (lane & 7) + (m & 1) * 8;
        int col = kk + (m >> 1) * 8;
        ldmx4(a0, a1, a2, a3, xs + (uint32_t)(row * 72 + col) * 2);
      }
#pragma unroll
      for (int j = 0; j < 16; j += 2) {
        uint32_t b0, b1, b2, b3;
        int m = lane >> 3;
        int row = j * 8 + (lane & 7) + (m >> 1) * 8;
        int col = kk + (m & 1) * 8;
        ldmx4(b0, b1, b2, b3, ws + (uint32_t)(row * 72 + col) * 2);
        mma16816(acc[j],     a0, a1, a2, a3, b0, b1);
        mma16816(acc[j + 1], a0, a1, a2, a3, b2, b3);
      }
    }
    __syncthreads();
  }

  // epilogue: bf16 out
  bf16* og = out + ((size_t)bh * N_ + n0) * E + e0;
#pragma unroll
  for (int j = 0; j < 16; ++j) {
    int col = j * 8 + tig * 2;
    *(uint32_t*)(og + (size_t)(m0 + gid) * E + col)     = packbf(acc[j][0], acc[j][1]);
    *(uint32_t*)(og + (size_t)(m0 + gid + 8) * E + col) = packbf(acc[j][2], acc[j][3]);
  }
}

// ---------------------------------------------------------------------------
// Fused causal relu-attention + residual, bf16 HMMA.
// Block: (v-chunk 128, q-tile 64, b). 4 warps; warp owns 16 q-rows.
// S kept in registers (C-frag -> A-frag repack), V via ldmatrix.trans.
// ---------------------------------------------------------------------------
__global__ __launch_bounds__(128) void attn_mma(const float* __restrict__ X,
                                                float* __restrict__ out) {
  extern __shared__ bf16 sm[];
  bf16* Qs = sm;               // [64][136]
  bf16* Ks = Qs + 64 * 136;    // [64][136]
  bf16* Vs = Ks + 64 * 136;    // [64][136]

  const int b  = blockIdx.z;
  const int qi = blockIdx.y;
  const int q0 = qi * 64;
  const int v0 = blockIdx.x * 128;
  const int tid = threadIdx.x, warp = tid >> 5, lane = tid & 31;
  const int gid = lane >> 2, tig = lane & 3;
  const uint32_t qs = smem_u32(Qs), ks = smem_u32(Ks), vs = smem_u32(Vs);
  const float invN = 1.0f / (float)N_;

  const int r0 = q0 + warp * 16 + gid;  // this thread's q rows
  const int r1 = r0 + 8;

  float oacc[16][4] = {};  // O[16 rows][128 v] per warp

  for (int h = 0; h < H_; ++h) {
    const size_t bh = (size_t)(b * H_ + h);
    const bf16* Qg = g_Q + (bh * N_ + q0) * DK_;
    __syncthreads();
#pragma unroll
    for (int r = 0; r < 8; ++r) {
      int f = tid + 128 * r;
      int row = f >> 4, c8 = (f & 15) * 8;
      *(uint4*)&Qs[row * 136 + c8] = *(const uint4*)(Qg + (size_t)row * DK_ + c8);
    }
    __syncthreads();

    for (int kt = 0; kt <= qi; ++kt) {
      const int k0 = kt * 64;
      const bf16* Kg = g_K + (bh * N_ + k0) * DK_;
      const bf16* Vg = g_V + (bh * N_ + k0) * DV_ + v0;
#pragma unroll
      for (int r = 0; r < 8; ++r) {
        int f = tid + 128 * r;
        int row = f >> 4, c8 = (f & 15) * 8;
        *(uint4*)&Ks[row * 136 + c8] = *(const uint4*)(Kg + (size_t)row * DK_ + c8);
        *(uint4*)&Vs[row * 136 + c8] = *(const uint4*)(Vg + (size_t)row * DV_ + c8);
      }
      __syncthreads();

      // ---- S = Q K^T  (16 q-rows x 64 keys per warp) ----
      float sf[8][4] = {};
#pragma unroll
      for (int kk = 0; kk < DK_; kk += 16) {
        uint32_t a0, a1, a2, a3;
        {
          int m = lane >> 3;
          int row = warp * 16 + (lane & 7) + (m & 1) * 8;
          int col = kk + (m >> 1) * 8;
          ldmx4(a0, a1, a2, a3, qs + (uint32_t)(row * 136 + col) * 2);
        }
#pragma unroll
        for (int j = 0; j < 8; j += 2) {
          uint32_t b0, b1, b2, b3;
          int m = lane >> 3;
          int row = j * 8 + (lane & 7) + (m >> 1) * 8;
          int col = kk + (m & 1) * 8;
          ldmx4(b0, b1, b2, b3, ks + (uint32_t)(row * 136 + col) * 2);
          mma16816(sf[j],     a0, a1, a2, a3, b0, b1);
          mma16816(sf[j + 1], a0, a1, a2, a3, b2, b3);
        }
      }

      // ---- mask + relu + /N, repack C-frags as A-frags (bf16) ----
      uint32_t sA[4][4];
#pragma unroll
      for (int g = 0; g < 8; ++g) {
        int key = k0 + g * 8 + tig * 2;
        float v0f = (key     <= r0) ? fmaxf(sf[g][0], 0.f) * invN : 0.f;
        float v1f = (key + 1 <= r0) ? fmaxf(sf[g][1], 0.f) * invN : 0.f;
        float v2f = (key     <= r1) ? fmaxf(sf[g][2], 0.f) * invN : 0.f;
        float v3f = (key + 1 <= r1) ? fmaxf(sf[g][3], 0.f) * invN : 0.f;
        int ki = g >> 1;
        if (!(g & 1)) {
          sA[ki][0] = packbf(v0f, v1f);
          sA[ki][1] = packbf(v2f, v3f);
        } else {
          sA[ki][2] = packbf(v0f, v1f);
          sA[ki][3] = packbf(v2f, v3f);
        }
      }

      // ---- O += S @ V ----
#pragma unroll
      for (int ki = 0; ki < 4; ++ki) {
#pragma unroll
        for (int j = 0; j < 16; j += 2) {
          uint32_t b0, b1, b2, b3;
          int m = lane >> 3;
          int row = ki * 16 + (m & 1) * 8 + (lane & 7);
          int col = j * 8 + (m >> 1) * 8;
          ldmx4t(b0, b1, b2, b3, vs + (uint32_t)(row * 136 + col) * 2);
          mma16816(oacc[j],     sA[ki][0], sA[ki][1], sA[ki][2], sA[ki][3], b0, b1);
          mma16816(oacc[j + 1], sA[ki][0], sA[ki][1], sA[ki][2], sA[ki][3], b2, b3);
        }
      }
      __syncthreads();
    }
  }

  // ---- epilogue: out = x + O (fp32) ----
  const float* xg = X + ((size_t)b * N_ + q0 + warp * 16) * DV_ + v0;
  float* og = out + ((size_t)b * N_ + q0 + warp * 16) * DV_ + v0;
#pragma unroll
  for (int j = 0; j < 16; ++j) {
    int col = j * 8 + tig * 2;
    const float* xp0 = xg + (size_t)gid * DV_ + col;
    const float* xp1 = xg + (size_t)(gid + 8) * DV_ + col;
    float2 a = *(const float2*)xp0;
    float2 c = *(const float2*)xp1;
    *(float2*)(og + (size_t)gid * DV_ + col) =
        make_float2(a.x + oacc[j][0], a.y + oacc[j][1]);
    *(float2*)(og + (size_t)(gid + 8) * DV_ + col) =
        make_float2(c.x + oacc[j][2], c.y + oacc[j][3]);
  }
}

// ---------------------------------------------------------------------------
extern "C" void kernel_launch(void* const* d_in, const int* in_sizes, int n_in,
                              void* d_out, int out_size) {
  const float* x  = (const float*)d_in[0];
  const float* Wq = (const float*)d_in[1];
  const float* Wk = (const float*)d_in[2];
  const float* Wv = (const float*)d_in[3];
  float* out = (float*)d_out;

  bf16 *Xb, *Wqb, *Wkb, *Wvb, *Qb, *Kb, *Vb;
  cudaGetSymbolAddress((void**)&Xb,  g_Xb);
  cudaGetSymbolAddress((void**)&Wqb, g_Wqb);
  cudaGetSymbolAddress((void**)&Wkb, g_Wkb);
  cudaGetSymbolAddress((void**)&Wvb, g_Wvb);
  cudaGetSymbolAddress((void**)&Qb,  g_Q);
  cudaGetSymbolAddress((void**)&Kb,  g_K);
  cudaGetSymbolAddress((void**)&Vb,  g_V);

  auto cast = [&](const float* s, bf16* d, int n) {
    int n4 = n / 4;
    cast_kernel<<<(n4 + 255) / 256, 256>>>(s, d, n4);
  };
  cast(x,  Xb,  B_ * N_ * D_);
  cast(Wq, Wqb, H_ * DK_ * D_);
  cast(Wk, Wkb, H_ * DK_ * D_);
  cast(Wv, Wvb, H_ * DV_ * D_);

  proj_mma<DK_><<<dim3(1, 16, 16), 256>>>(Xb, Wqb, Qb);
  proj_mma<DK_><<<dim3(1, 16, 16), 256>>>(Xb, Wkb, Kb);
  proj_mma<DV_><<<dim3(8, 16, 16), 256>>>(Xb, Wvb, Vb);

  size_t smem = (size_t)3 * 64 * 136 * sizeof(bf16);  // 52224 B
  static bool attr_done = false;
  if (!attr_done) {
    cudaFuncSetAttribute(attn_mma, cudaFuncAttributeMaxDynamicSharedMemorySize,
                         (int)smem);
    attr_done = true;
  }
  attn_mma<<<dim3(8, 32, 2), 128, smem>>>(x, out);
}